// round 17
// baseline (speedup 1.0000x reference)
#include <cuda_runtime.h>
#include <cuda_bf16.h>

// AdEx neuron sim, sm_103a. Round 15.
// R14 phase-batched structure + ping-pong double buffer:
//   iter k: [burst-load bufB <- rows t+16..t+31] [compute group t from bufA]
//           [burst-store] ; roles swap (outer loop unrolled x2, zero copies).
// Removes the 16-MOV copy phase and doubles prefetch-to-consume distance.
// Numerics: R11 step verbatim — rel_err 2.313e-8.

#define G 16   // group size

#define C_EL        (-70.6e-3f)
#define C_VT        (-50.4e-3f)
#define C_GL        (30.0e-9f)
#define C_DTCM      (3.5587188612099645e6f)   // DT / CM
#define C_DTTAUW    (6.944444444444445e-3f)   // DT / TAUW
#define C_A         (4.0e-9f)
#define C_B         (0.0805e-9f)
// y = (v - VT)*500*log2e + log2(GL*DELTAT)  ==  fma(v, C_YSLOPE, C_YB2)
#define C_YSLOPE    (721.3475204444817f)      // 500 * log2(e)
#define C_YB2       (2.3996684904f)           // log2(6e-11) - VT*C_YSLOPE

// p1 = spiked last step, p2 = spiked two steps ago  (REF_STEPS = 2)
// E carries GL*DELTAT*exp((v - VT)/DELTAT) for the CURRENT v.  (R11 verbatim)
__device__ __forceinline__ void adex_step(float It, float E_EL,
                                          float& v, float& E, float& c,
                                          bool& p1, bool& p2, float& v_out) {
    bool in_ref = p1 | p2;

    float s23 = It - c;                 // off critical path
    float ve  = v - C_EL;

    float s1 = fmaf(-C_GL, ve, E);
    float s4 = s1 + s23;
    float v_new = fmaf(C_DTCM, s4, v);

    bool raw   = (v_new >= C_VT);
    bool sel   = raw | in_ref;
    bool spike = raw & (!in_ref);

    // speculative exp for next step (FSETP overlaps EX2)
    float y = fmaf(v_new, C_YSLOPE, C_YB2);
    float E_spec;
    asm("ex2.approx.ftz.f32 %0, %1;" : "=f"(E_spec) : "f"(y));

    float c_mid = fmaf(C_A, ve, -c);
    float c_new = fmaf(C_DTTAUW, c_mid, c);

    v = sel ? C_EL : v_new;
    E = sel ? E_EL : E_spec;
    c = spike ? (c_new + C_B) : c_new;
    p2 = p1;
    p1 = spike;
    v_out = v;
}

__device__ __forceinline__ float make_E(float v) {
    float y = fmaf(v, C_YSLOPE, C_YB2);
    float E;
    asm("ex2.approx.ftz.f32 %0, %1;" : "=f"(E) : "f"(y));
    return E;
}

template<int N_STATIC>
__global__ void __launch_bounds__(256) adex_kernel(
    const float* __restrict__ I,    // [T, N]
    const float* __restrict__ v0,
    const float* __restrict__ c0,
    const int*   __restrict__ ref0,
    float*       __restrict__ out,  // [T, N]
    int T, int N_rt)
{
    const int N = (N_STATIC > 0) ? N_STATIC : N_rt;
    int n = blockIdx.x * blockDim.x + threadIdx.x;
    if (n >= N) return;

    float v   = v0[n];
    float c   = c0[n];
    int   ref = ref0[n];
    bool  p1  = (ref > 1);        // spiked last step
    bool  p2  = (ref == 1);       // spiked two steps ago
    if (p1 | p2) v = C_EL;        // invariant: v==EL while refractory

    const float E_EL = make_E(C_EL);
    float E = make_E(v);

    const float* Ip = I + n;
    float*       Op = out + n;

    // prime bufA with rows 0..G-1
    float bufA[G], bufB[G];
    #pragma unroll
    for (int u = 0; u < G; ++u)
        bufA[u] = (u < T) ? __ldcs(Ip + (size_t)u * N) : 0.0f;

    // steady: pairs of groups, ping-pong; all loads unguarded (t+3G <= T)
    int t = 0;
    for (; t + 3 * G <= T; t += 2 * G) {
        {   // group at t, consume bufA, prefetch into bufB (rows t+G..t+2G-1)
            const float* Ipn = Ip + (size_t)(t + G) * N;
            float*       Opt = Op + (size_t)t * N;
            #pragma unroll
            for (int u = 0; u < G; ++u)
                bufB[u] = __ldcs(Ipn + (size_t)u * N);
            float ov[G];
            #pragma unroll
            for (int u = 0; u < G; ++u)
                adex_step(bufA[u], E_EL, v, E, c, p1, p2, ov[u]);
            #pragma unroll
            for (int u = 0; u < G; ++u)
                __stcs(Opt + (size_t)u * N, ov[u]);
        }
        {   // group at t+G, consume bufB, prefetch into bufA (rows t+2G..t+3G-1)
            const float* Ipn = Ip + (size_t)(t + 2 * G) * N;
            float*       Opt = Op + (size_t)(t + G) * N;
            #pragma unroll
            for (int u = 0; u < G; ++u)
                bufA[u] = __ldcs(Ipn + (size_t)u * N);
            float ov[G];
            #pragma unroll
            for (int u = 0; u < G; ++u)
                adex_step(bufB[u], E_EL, v, E, c, p1, p2, ov[u]);
            #pragma unroll
            for (int u = 0; u < G; ++u)
                __stcs(Opt + (size_t)u * N, ov[u]);
        }
    }
    // invariant here: bufA holds rows t..t+G-1 (those < T)

    // epilogue 1: consume resident rows, refill bufA guarded
    #pragma unroll
    for (int u = 0; u < G; ++u) {
        int row = t + u;
        if (row < T) {
            float It = bufA[u];
            int tt = row + G;
            float nx = (tt < T) ? __ldcs(Ip + (size_t)tt * N) : 0.0f;
            float ov1;
            adex_step(It, E_EL, v, E, c, p1, p2, ov1);
            __stcs(Op + (size_t)row * N, ov1);
            bufA[u] = nx;
        }
    }
    t += G;

    // epilogue 2: remaining < G rows
    #pragma unroll
    for (int u = 0; u < G; ++u) {
        int row = t + u;
        if (row < T) {
            float ov1;
            adex_step(bufA[u], E_EL, v, E, c, p1, p2, ov1);
            __stcs(Op + (size_t)row * N, ov1);
        }
    }
}

extern "C" void kernel_launch(void* const* d_in, const int* in_sizes, int n_in,
                              void* d_out, int out_size)
{
    const float* I    = (const float*)d_in[0];
    const float* v0   = (const float*)d_in[1];
    const float* c0   = (const float*)d_in[2];
    const int*   ref0 = (const int*)  d_in[3];
    float*       out  = (float*)d_out;

    int N = in_sizes[1];
    int T = in_sizes[0] / N;

    int threads = 256;
    int blocks  = (N + threads - 1) / threads;

    if (N == 100000) {
        adex_kernel<100000><<<blocks, threads>>>(I, v0, c0, ref0, out, T, N);
    } else {
        adex_kernel<0><<<blocks, threads>>>(I, v0, c0, ref0, out, T, N);
    }
}